// round 8
// baseline (speedup 1.0000x reference)
#include <cuda_runtime.h>
#include <math_constants.h>

#define BB 32
#define TT 4096
#define DD 512
#define SS 8               // splits of T per batch
#define CHUNK (TT / SS)    // 512 rows per CTA
#define NTHREADS 256
#define NWARPS 8
#define ROWS_PER_IT (2 * NWARPS)   // each warp handles 2 rows per iteration

// Scratch (device globals: no allocation allowed in kernel_launch)
__device__ float g_cai[BB * TT];          // raw logits
__device__ float g_part_m[BB * SS];       // per-split running max
__device__ float g_part_d[BB * SS];       // per-split denom
__device__ float g_part_c[BB * SS * DD];  // per-split weighted sums

// ---------------------------------------------------------------------------
// Pass 1: single sweep over K. Each CTA handles one (batch, T-chunk).
// Each warp processes TWO K rows per iteration: 8 independent float4 loads
// issued up front before dependent math. __launch_bounds__(256, 2) caps regs
// at 128 so 2 CTAs/SM (16 warps) stay resident -> ~16 KB/SM loads in flight,
// covering most of the ~600-cycle DRAM latency at the per-SM BW share.
// Online softmax with register accumulator (16 floats/lane = 512 dims/warp).
// ---------------------------------------------------------------------------
__global__ __launch_bounds__(NTHREADS, 2) void pass1_kernel(
    const float* __restrict__ q,
    const float* __restrict__ K,
    const float* __restrict__ W,
    const float* __restrict__ bias)
{
    const int s    = blockIdx.x;
    const int b    = blockIdx.y;
    const int tid  = threadIdx.x;
    const int wid  = tid >> 5;
    const int lane = tid & 31;

    __shared__ float r_sm[DD];
    __shared__ float red_m[NWARPS];
    __shared__ float red_d[NWARPS];
    __shared__ float c_sm[NWARPS][DD];   // 16 KB

    // r = q[b,:] * W[:,0]
    for (int i = tid; i < DD; i += NTHREADS)
        r_sm[i] = q[b * DD + i] * W[i];
    __syncthreads();

    // Pull r into registers matching the K-load layout:
    // lane owns dims { j*128 + lane*4 + c : j<4, c<4 }
    float rv[16];
    #pragma unroll
    for (int j = 0; j < 4; j++) {
        float4 v = *(const float4*)&r_sm[j * 128 + lane * 4];
        rv[j * 4 + 0] = v.x; rv[j * 4 + 1] = v.y;
        rv[j * 4 + 2] = v.z; rv[j * 4 + 3] = v.w;
    }
    const float bval = __ldg(bias);

    float m    = -CUDART_INF_F;
    float dsum = 0.0f;
    float acc[16];
    #pragma unroll
    for (int k = 0; k < 16; k++) acc[k] = 0.0f;

    const float* Kb = K + ((size_t)b * TT + (size_t)s * CHUNK) * DD;
    const int t0 = s * CHUNK;

    // CHUNK = 512; warp handles rows {2*wid, 2*wid+1, +16, ...}.
    // unroll 1: keep live ranges small so the 128-reg cap doesn't spill.
    #pragma unroll 1
    for (int t = 2 * wid; t < CHUNK; t += ROWS_PER_IT) {
        const float4* row0 = (const float4*)(Kb + (size_t)t * DD);
        const float4* row1 = (const float4*)(Kb + (size_t)(t + 1) * DD);

        // Issue all 8 loads before any dependent math (MLP = 8 per warp)
        float4 v0[4], v1[4];
        #pragma unroll
        for (int j = 0; j < 4; j++) v0[j] = row0[j * 32 + lane];
        #pragma unroll
        for (int j = 0; j < 4; j++) v1[j] = row1[j * 32 + lane];

        float kv0[16], kv1[16];
        float dot0 = 0.0f, dot1 = 0.0f;
        #pragma unroll
        for (int j = 0; j < 4; j++) {
            kv0[j * 4 + 0] = v0[j].x; kv0[j * 4 + 1] = v0[j].y;
            kv0[j * 4 + 2] = v0[j].z; kv0[j * 4 + 3] = v0[j].w;
            dot0 += v0[j].x * rv[j * 4 + 0] + v0[j].y * rv[j * 4 + 1]
                  + v0[j].z * rv[j * 4 + 2] + v0[j].w * rv[j * 4 + 3];
            kv1[j * 4 + 0] = v1[j].x; kv1[j * 4 + 1] = v1[j].y;
            kv1[j * 4 + 2] = v1[j].z; kv1[j * 4 + 3] = v1[j].w;
            dot1 += v1[j].x * rv[j * 4 + 0] + v1[j].y * rv[j * 4 + 1]
                  + v1[j].z * rv[j * 4 + 2] + v1[j].w * rv[j * 4 + 3];
        }

        // Two independent butterfly reductions (interleave in the scheduler)
        #pragma unroll
        for (int off = 16; off > 0; off >>= 1) {
            dot0 += __shfl_xor_sync(0xffffffffu, dot0, off);
            dot1 += __shfl_xor_sync(0xffffffffu, dot1, off);
        }

        const float cai0 = dot0 + bval;
        const float cai1 = dot1 + bval;
        if (lane == 0) {
            // rows t, t+1 are adjacent: one STG.64 instead of two STG.32
            float2 cpair; cpair.x = cai0; cpair.y = cai1;
            *(float2*)&g_cai[b * TT + t0 + t] = cpair;
        }

        // Fused 2-row online-softmax update (3 exps per 2 rows).
        // A branch to skip the rescale when M2==m costs more
        // (BSSY/BSYNC ~35 cyc) than the 16 predicated FMAs it saves.
        const float M2    = fmaxf(fmaxf(m, cai0), cai1);
        const float scale = __expf(m - M2);       // first iter: exp(-inf)=0
        const float p0    = __expf(cai0 - M2);
        const float p1    = __expf(cai1 - M2);
        dsum = dsum * scale + p0 + p1;
        #pragma unroll
        for (int k = 0; k < 16; k++)
            acc[k] = acc[k] * scale + (p0 * kv0[k] + p1 * kv1[k]);
        m = M2;
    }

    // ---- CTA merge of 8 warp states ----
    if (lane == 0) { red_m[wid] = m; red_d[wid] = dsum; }
    __syncthreads();

    float M = red_m[0];
    #pragma unroll
    for (int w = 1; w < NWARPS; w++) M = fmaxf(M, red_m[w]);

    const float e = __expf(m - M);
    #pragma unroll
    for (int j = 0; j < 4; j++) {
        float4 v;
        v.x = acc[j * 4 + 0] * e; v.y = acc[j * 4 + 1] * e;
        v.z = acc[j * 4 + 2] * e; v.w = acc[j * 4 + 3] * e;
        *(float4*)&c_sm[wid][j * 128 + lane * 4] = v;
    }
    __syncthreads();

    if (tid == 0) {
        float Dt = 0.0f;
        #pragma unroll
        for (int w = 0; w < NWARPS; w++)
            Dt += red_d[w] * __expf(red_m[w] - M);
        g_part_m[b * SS + s] = M;
        g_part_d[b * SS + s] = Dt;
    }

    for (int i = tid; i < DD; i += NTHREADS) {
        float sum = 0.0f;
        #pragma unroll
        for (int w = 0; w < NWARPS; w++)
            sum += c_sm[w][i];
        g_part_c[((size_t)b * SS + s) * DD + i] = sum;
    }
}

// ---------------------------------------------------------------------------
// Pass 2 (fused epilogue): one CTA per batch.
//   a) merge SS split-partials -> final (M, Dsum), write c[b,:]
//   b) write ca[b,:] = exp(cai - M) / Dsum  (float4-vectorized, 4/thread x4)
// Epilogue traffic ~1.3 MB total -> launch-overhead-dominated; fusing removes
// one kernel boundary and the g_final round-trip through DRAM.
// ---------------------------------------------------------------------------
__global__ __launch_bounds__(NTHREADS) void pass2_kernel(
    float* __restrict__ out_c, float* __restrict__ out_ca)
{
    const int b   = blockIdx.x;
    const int tid = threadIdx.x;

    __shared__ float sm[SS];
    __shared__ float sd[SS];
    if (tid < SS) {
        sm[tid] = g_part_m[b * SS + tid];
        sd[tid] = g_part_d[b * SS + tid];
    }
    __syncthreads();

    float M = sm[0];
    #pragma unroll
    for (int s = 1; s < SS; s++) M = fmaxf(M, sm[s]);

    float es[SS];
    float Dt = 0.0f;
    #pragma unroll
    for (int s = 0; s < SS; s++) {
        es[s] = __expf(sm[s] - M);
        Dt += sd[s] * es[s];
    }
    const float inv = 1.0f / Dt;

    // c[b,:]
    for (int i = tid; i < DD; i += NTHREADS) {
        float sum = 0.0f;
        #pragma unroll
        for (int s = 0; s < SS; s++)
            sum += g_part_c[((size_t)b * SS + s) * DD + i] * es[s];
        out_c[b * DD + i] = sum * inv;
    }

    // ca[b,:] : TT = 4096 elems, 1024 float4s, 256 threads -> 4 each
    const float* cai_b = &g_cai[b * TT];
    float*       ca_b  = &out_ca[b * TT];
    #pragma unroll
    for (int it = 0; it < TT / (4 * NTHREADS); it++) {
        const int i4 = (it * NTHREADS + tid) * 4;
        float4 v = *(const float4*)&cai_b[i4];
        float4 o;
        o.x = __expf(v.x - M) * inv;
        o.y = __expf(v.y - M) * inv;
        o.z = __expf(v.z - M) * inv;
        o.w = __expf(v.w - M) * inv;
        *(float4*)&ca_b[i4] = o;
    }
}

extern "C" void kernel_launch(void* const* d_in, const int* in_sizes, int n_in,
                              void* d_out, int out_size)
{
    const float* q    = (const float*)d_in[0];   // [B, D]
    const float* K    = (const float*)d_in[1];   // [B, T, D]
    const float* W    = (const float*)d_in[2];   // [D, 1]
    const float* bias = (const float*)d_in[3];   // [1]

    float* out    = (float*)d_out;
    float* out_c  = out;              // [B, D]    = 16384 floats
    float* out_ca = out + BB * DD;    // [B, T, 1] = 131072 floats

    dim3 grid1(SS, BB);
    pass1_kernel<<<grid1, NTHREADS>>>(q, K, W, bias);
    pass2_kernel<<<BB, NTHREADS>>>(out_c, out_ca);
}

// round 10
// speedup vs baseline: 1.0087x; 1.0087x over previous
#include <cuda_runtime.h>
#include <math_constants.h>

#define BB 32
#define TT 4096
#define DD 512
#define SS 8               // splits of T per batch
#define CHUNK (TT / SS)    // 512 rows per CTA
#define NTHREADS 256
#define NWARPS 8
#define ROWS_PER_IT (2 * NWARPS)   // each warp handles 2 rows per iteration
#define ESPLIT 8           // epilogue CTAs per batch

// Scratch (device globals: no allocation allowed in kernel_launch)
__device__ float g_cai[BB * TT];          // raw logits
__device__ float g_part_m[BB * SS];       // per-split running max
__device__ float g_part_d[BB * SS];       // per-split denom
__device__ float g_part_c[BB * SS * DD];  // per-split weighted sums

// ---------------------------------------------------------------------------
// Pass 1: single sweep over K. Each CTA handles one (batch, T-chunk).
// Each warp processes TWO K rows per iteration: 8 independent float4 loads
// issued up front before dependent math. __launch_bounds__(256, 2) caps regs
// at 128 so 2 CTAs/SM (16 warps) stay resident -> ~16 KB/SM loads in flight,
// covering most of the ~600-cycle DRAM latency at the per-SM BW share.
// Online softmax with register accumulator (16 floats/lane = 512 dims/warp).
// MEASURED (R8): total 51.7us with this pass1 ~43us vs ~39us HBM floor.
// FROZEN — do not touch without a pass1-specific profile.
// ---------------------------------------------------------------------------
__global__ __launch_bounds__(NTHREADS, 2) void pass1_kernel(
    const float* __restrict__ q,
    const float* __restrict__ K,
    const float* __restrict__ W,
    const float* __restrict__ bias)
{
    const int s    = blockIdx.x;
    const int b    = blockIdx.y;
    const int tid  = threadIdx.x;
    const int wid  = tid >> 5;
    const int lane = tid & 31;

    __shared__ float r_sm[DD];
    __shared__ float red_m[NWARPS];
    __shared__ float red_d[NWARPS];
    __shared__ float c_sm[NWARPS][DD];   // 16 KB

    // r = q[b,:] * W[:,0]
    for (int i = tid; i < DD; i += NTHREADS)
        r_sm[i] = q[b * DD + i] * W[i];
    __syncthreads();

    // Pull r into registers matching the K-load layout:
    // lane owns dims { j*128 + lane*4 + c : j<4, c<4 }
    float rv[16];
    #pragma unroll
    for (int j = 0; j < 4; j++) {
        float4 v = *(const float4*)&r_sm[j * 128 + lane * 4];
        rv[j * 4 + 0] = v.x; rv[j * 4 + 1] = v.y;
        rv[j * 4 + 2] = v.z; rv[j * 4 + 3] = v.w;
    }
    const float bval = __ldg(bias);

    float m    = -CUDART_INF_F;
    float dsum = 0.0f;
    float acc[16];
    #pragma unroll
    for (int k = 0; k < 16; k++) acc[k] = 0.0f;

    const float* Kb = K + ((size_t)b * TT + (size_t)s * CHUNK) * DD;
    const int t0 = s * CHUNK;

    // CHUNK = 512; warp handles rows {2*wid, 2*wid+1, +16, ...}.
    // unroll 1: keep live ranges small so the 128-reg cap doesn't spill.
    #pragma unroll 1
    for (int t = 2 * wid; t < CHUNK; t += ROWS_PER_IT) {
        const float4* row0 = (const float4*)(Kb + (size_t)t * DD);
        const float4* row1 = (const float4*)(Kb + (size_t)(t + 1) * DD);

        // Issue all 8 loads before any dependent math (MLP = 8 per warp)
        float4 v0[4], v1[4];
        #pragma unroll
        for (int j = 0; j < 4; j++) v0[j] = row0[j * 32 + lane];
        #pragma unroll
        for (int j = 0; j < 4; j++) v1[j] = row1[j * 32 + lane];

        float kv0[16], kv1[16];
        float dot0 = 0.0f, dot1 = 0.0f;
        #pragma unroll
        for (int j = 0; j < 4; j++) {
            kv0[j * 4 + 0] = v0[j].x; kv0[j * 4 + 1] = v0[j].y;
            kv0[j * 4 + 2] = v0[j].z; kv0[j * 4 + 3] = v0[j].w;
            dot0 += v0[j].x * rv[j * 4 + 0] + v0[j].y * rv[j * 4 + 1]
                  + v0[j].z * rv[j * 4 + 2] + v0[j].w * rv[j * 4 + 3];
            kv1[j * 4 + 0] = v1[j].x; kv1[j * 4 + 1] = v1[j].y;
            kv1[j * 4 + 2] = v1[j].z; kv1[j * 4 + 3] = v1[j].w;
            dot1 += v1[j].x * rv[j * 4 + 0] + v1[j].y * rv[j * 4 + 1]
                  + v1[j].z * rv[j * 4 + 2] + v1[j].w * rv[j * 4 + 3];
        }

        // Two independent butterfly reductions (interleave in the scheduler)
        #pragma unroll
        for (int off = 16; off > 0; off >>= 1) {
            dot0 += __shfl_xor_sync(0xffffffffu, dot0, off);
            dot1 += __shfl_xor_sync(0xffffffffu, dot1, off);
        }

        const float cai0 = dot0 + bval;
        const float cai1 = dot1 + bval;
        if (lane == 0) {
            // rows t, t+1 are adjacent: one STG.64 instead of two STG.32
            float2 cpair; cpair.x = cai0; cpair.y = cai1;
            *(float2*)&g_cai[b * TT + t0 + t] = cpair;
        }

        // Fused 2-row online-softmax update (3 exps per 2 rows).
        const float M2    = fmaxf(fmaxf(m, cai0), cai1);
        const float scale = __expf(m - M2);       // first iter: exp(-inf)=0
        const float p0    = __expf(cai0 - M2);
        const float p1    = __expf(cai1 - M2);
        dsum = dsum * scale + p0 + p1;
        #pragma unroll
        for (int k = 0; k < 16; k++)
            acc[k] = acc[k] * scale + (p0 * kv0[k] + p1 * kv1[k]);
        m = M2;
    }

    // ---- CTA merge of 8 warp states ----
    if (lane == 0) { red_m[wid] = m; red_d[wid] = dsum; }
    __syncthreads();

    float M = red_m[0];
    #pragma unroll
    for (int w = 1; w < NWARPS; w++) M = fmaxf(M, red_m[w]);

    const float e = __expf(m - M);
    #pragma unroll
    for (int j = 0; j < 4; j++) {
        float4 v;
        v.x = acc[j * 4 + 0] * e; v.y = acc[j * 4 + 1] * e;
        v.z = acc[j * 4 + 2] * e; v.w = acc[j * 4 + 3] * e;
        *(float4*)&c_sm[wid][j * 128 + lane * 4] = v;
    }
    __syncthreads();

    if (tid == 0) {
        float Dt = 0.0f;
        #pragma unroll
        for (int w = 0; w < NWARPS; w++)
            Dt += red_d[w] * __expf(red_m[w] - M);
        g_part_m[b * SS + s] = M;
        g_part_d[b * SS + s] = Dt;
    }

    for (int i = tid; i < DD; i += NTHREADS) {
        float sum = 0.0f;
        #pragma unroll
        for (int w = 0; w < NWARPS; w++)
            sum += c_sm[w][i];
        g_part_c[((size_t)b * SS + s) * DD + i] = sum;
    }
}

// ---------------------------------------------------------------------------
// Pass 2 (widened epilogue): grid (ESPLIT, BB) = 256 CTAs.
// R8 profile showed the 32-CTA version at 8.2us, occ 12%, 129 GB/s — pure
// parallelism starvation. Each CTA now redundantly recomputes the trivial
// (M, Dsum) merge (8 values) and owns a 1/ESPLIT slice of both outputs:
//   c slice:  DD/ESPLIT = 64 dims
//   ca slice: TT/ESPLIT = 512 elems (128 float4s)
// Predicted: ~2.5us (launch-overhead floor).
// ---------------------------------------------------------------------------
__global__ __launch_bounds__(NTHREADS) void pass2_kernel(
    float* __restrict__ out_c, float* __restrict__ out_ca)
{
    const int e   = blockIdx.x;     // epilogue slice
    const int b   = blockIdx.y;     // batch
    const int tid = threadIdx.x;

    // Every thread recomputes the merge from the 8 partials (broadcast loads)
    float M = -CUDART_INF_F;
    #pragma unroll
    for (int s = 0; s < SS; s++) M = fmaxf(M, g_part_m[b * SS + s]);

    float es[SS];
    float Dt = 0.0f;
    #pragma unroll
    for (int s = 0; s < SS; s++) {
        es[s] = __expf(g_part_m[b * SS + s] - M);
        Dt += g_part_d[b * SS + s] * es[s];
    }
    const float inv = 1.0f / Dt;

    // c slice: dims [e*64, (e+1)*64)
    const int dbase = e * (DD / ESPLIT);
    if (tid < DD / ESPLIT) {
        const int i = dbase + tid;
        float sum = 0.0f;
        #pragma unroll
        for (int s = 0; s < SS; s++)
            sum += g_part_c[((size_t)b * SS + s) * DD + i] * es[s];
        out_c[b * DD + i] = sum * inv;
    }

    // ca slice: elems [e*512, (e+1)*512) -> 128 float4s, threads 0..127
    if (tid < (TT / ESPLIT) / 4) {
        const int i4 = e * (TT / ESPLIT) + tid * 4;
        float4 v = *(const float4*)&g_cai[b * TT + i4];
        float4 o;
        o.x = __expf(v.x - M) * inv;
        o.y = __expf(v.y - M) * inv;
        o.z = __expf(v.z - M) * inv;
        o.w = __expf(v.w - M) * inv;
        *(float4*)&out_ca[b * TT + i4] = o;
    }
}

extern "C" void kernel_launch(void* const* d_in, const int* in_sizes, int n_in,
                              void* d_out, int out_size)
{
    const float* q    = (const float*)d_in[0];   // [B, D]
    const float* K    = (const float*)d_in[1];   // [B, T, D]
    const float* W    = (const float*)d_in[2];   // [D, 1]
    const float* bias = (const float*)d_in[3];   // [1]

    float* out    = (float*)d_out;
    float* out_c  = out;              // [B, D]    = 16384 floats
    float* out_ca = out + BB * DD;    // [B, T, 1] = 131072 floats

    dim3 grid1(SS, BB);
    pass1_kernel<<<grid1, NTHREADS>>>(q, K, W, bias);
    dim3 grid2(ESPLIT, BB);
    pass2_kernel<<<grid2, NTHREADS>>>(out_c, out_ca);
}